// round 10
// baseline (speedup 1.0000x reference)
#include <cuda_runtime.h>
#include <cuda_fp16.h>
#include <cstdint>

// ---------------------------------------------------------------- constants
#define N_TOKENS  65536
#define IN_DIM    2048
#define N_EXPERTS 64
#define TILE_M    256
#define BK        32
#define NITER     (IN_DIM / BK)       // 64
#define GROUP     4
#define NGROUPS   (NITER / GROUP)     // 16
#define NTHREADS  512                 // 16 warps: wm = w&7 (m-block), wk = w>>3 (k-half)
#define GRID_CTAS (N_TOKENS / TILE_M) // 256

// ---------------- smem map (bytes) ----------------
#define A_OFF_H2   20480
#define A_STAGE_B  40960
#define B_BASE     81920
#define B_CHUNK_B  10240
#define B_OFF_W2   5120
#define B_BUF_B    (GROUP * B_CHUNK_B)          // 40960
#define SMEM_BYTES (B_BASE + 2 * B_BUF_B)       // 163840 -> 1 CTA/SM

#define SPLIT_SCALE 2048.0f
#define INV_SCALE   (1.0f / 2048.0f)

__device__ __align__(16) __half Wpack_g[NITER * 2 * N_EXPERTS * BK];

// ---------------------------------------------------------------- helpers
__device__ __forceinline__ uint32_t smem_u32(const void* p) {
    uint32_t a;
    asm("{ .reg .u64 t; cvta.to.shared.u64 t, %1; cvt.u32.u64 %0, t; }" : "=r"(a) : "l"(p));
    return a;
}

__device__ __forceinline__ void ldsm4(uint32_t* r, uint32_t addr) {
    asm volatile("ldmatrix.sync.aligned.m8n8.x4.shared.b16 {%0,%1,%2,%3}, [%4];"
                 : "=r"(r[0]), "=r"(r[1]), "=r"(r[2]), "=r"(r[3]) : "r"(addr));
}

__device__ __forceinline__ void mma_f32(float* c, const uint32_t* a,
                                        uint32_t b0, uint32_t b1) {
    asm volatile(
        "mma.sync.aligned.m16n8k16.row.col.f32.f16.f16.f32 "
        "{%0,%1,%2,%3}, {%4,%5,%6,%7}, {%8,%9}, {%0,%1,%2,%3};"
        : "+f"(c[0]), "+f"(c[1]), "+f"(c[2]), "+f"(c[3])
        : "r"(a[0]), "r"(a[1]), "r"(a[2]), "r"(a[3]), "r"(b0), "r"(b1));
}

__device__ __forceinline__ void mma_f16(uint32_t* c, const uint32_t* a,
                                        uint32_t b0, uint32_t b1) {
    asm volatile(
        "mma.sync.aligned.m16n8k16.row.col.f16.f16.f16.f16 "
        "{%0,%1}, {%2,%3,%4,%5}, {%6,%7}, {%0,%1};"
        : "+r"(c[0]), "+r"(c[1])
        : "r"(a[0]), "r"(a[1]), "r"(a[2]), "r"(a[3]), "r"(b0), "r"(b1));
}

__device__ __forceinline__ void cp_async16(uint32_t dst, const void* src) {
    asm volatile("cp.async.ca.shared.global [%0], [%1], 16;" :: "r"(dst), "l"(src));
}
#define CP_COMMIT() asm volatile("cp.async.commit_group;" ::: "memory")
#define CP_WAIT0()  asm volatile("cp.async.wait_group 0;" ::: "memory")
#define BAR_PAIR(id) asm volatile("bar.sync %0, 64;" :: "r"(id) : "memory")

// ---------------------------------------------------------------- W split pre-kernel
__global__ void wsplit_kernel(const float* __restrict__ W) {
    int idx = blockIdx.x * 256 + threadIdx.x;
    int e = idx >> 11;
    int k = idx & 2047;
    float w = W[idx];
    __half h1 = __float2half_rn(w);
    float  r  = (w - __half2float(h1)) * SPLIT_SCALE;
    __half h2 = __float2half_rn(r);
    int j = k >> 5, kk = k & 31;
    Wpack_g[(size_t)j * 4096 + 0 * 2048 + e * 32 + kk] = h1;
    Wpack_g[(size_t)j * 4096 + 1 * 2048 + e * 32 + kk] = h2;
}

// ---------------------------------------------------------------- x conversion
__device__ __forceinline__ void cvt_store(char* Ab, uint32_t off, float4 v) {
    __half2 h1a = __floats2half2_rn(v.x, v.y);
    __half2 h1b = __floats2half2_rn(v.z, v.w);
    float2 fa = __half22float2(h1a);
    float2 fb = __half22float2(h1b);
    __half2 ra = __floats2half2_rn((v.x - fa.x) * SPLIT_SCALE, (v.y - fa.y) * SPLIT_SCALE);
    __half2 rb = __floats2half2_rn((v.z - fb.x) * SPLIT_SCALE, (v.w - fb.y) * SPLIT_SCALE);
    uint2 hh, rr;
    hh.x = *(uint32_t*)&h1a; hh.y = *(uint32_t*)&h1b;
    rr.x = *(uint32_t*)&ra;  rr.y = *(uint32_t*)&rb;
    *(uint2*)(Ab + off)            = hh;
    *(uint2*)(Ab + A_OFF_H2 + off) = rr;
}

// ---------------------------------------------------------------- main kernel
extern __shared__ __align__(16) char smch[];

__global__ void __launch_bounds__(NTHREADS, 1)
router_mma_kernel(const float* __restrict__ x, float* __restrict__ out) {
    const int tid  = threadIdx.x;
    const int w    = tid >> 5;
    const int lane = tid & 31;
    const int wm   = w & 7;
    const int wk   = w >> 3;
    const int tokenBase = blockIdx.x * TILE_M;
    const uint32_t sb = smem_u32(smch);

    const float* xbase = x + (size_t)(tokenBase + wm * 32 + wk * 16 + (lane >> 3)) * IN_DIM
                           + (lane & 7) * 4;
    const uint32_t st_base = (uint32_t)((wm * 32 + wk * 16 + (lane >> 3)) * 80
                                        + (lane & 7) * 8);

    const uint32_t ko = (uint32_t)wk * 32;
    const uint32_t a_ld = (uint32_t)((wm * 32 + (lane & 15)) * 80
                                     + ((lane >> 4) & 1) * 16) + ko;
    const uint32_t b_ld = (uint32_t)(((lane & 7) + ((lane >> 4) & 1) * 8) * 80
                                     + ((lane >> 3) & 1) * 16) + ko;

    float    accM[2][32];
    uint32_t accC[2][16];
    #pragma unroll
    for (int m = 0; m < 2; m++) {
        #pragma unroll
        for (int i = 0; i < 32; i++) accM[m][i] = 0.0f;
        #pragma unroll
        for (int i = 0; i < 16; i++) accC[m][i] = 0u;
    }

    float4 xr[4];

    // ================= prologue =================
    {
        #pragma unroll
        for (int i = 0; i < 4; i++) {
            int gs    = tid + 512 * i;
            int c     = gs >> 9;
            int ws    = gs & 511;
            int split = ws >> 8;
            int seg   = ws & 255;
            uint32_t dst = B_BASE + (uint32_t)c * B_CHUNK_B + (uint32_t)split * B_OFF_W2
                         + (uint32_t)(seg >> 2) * 80 + (uint32_t)(seg & 3) * 16;
            const char* src = (const char*)Wpack_g + (size_t)c * 8192
                            + (size_t)split * 4096 + (size_t)seg * 16;
            cp_async16(sb + dst, src);
        }
        CP_COMMIT();
        #pragma unroll
        for (int i = 0; i < 4; i++)
            xr[i] = *(const float4*)(xbase + (size_t)i * 4 * IN_DIM);
        #pragma unroll
        for (int i = 0; i < 4; i++)
            cvt_store(smch, st_base + (uint32_t)i * 320, xr[i]);
        CP_WAIT0();
        __syncthreads();
    }

    // ================= main loop =================
    for (int g = 0; g < NGROUPS; g++) {
        if (g + 1 < NGROUPS) {
            const uint32_t nbuf = B_BASE + (uint32_t)((g + 1) & 1) * B_BUF_B;
            const char* gsrc = (const char*)Wpack_g + (size_t)(g + 1) * GROUP * 8192;
            #pragma unroll
            for (int i = 0; i < 4; i++) {
                int gs    = tid + 512 * i;
                int c     = gs >> 9;
                int ws    = gs & 511;
                int split = ws >> 8;
                int seg   = ws & 255;
                uint32_t dst = nbuf + (uint32_t)c * B_CHUNK_B + (uint32_t)split * B_OFF_W2
                             + (uint32_t)(seg >> 2) * 80 + (uint32_t)(seg & 3) * 16;
                cp_async16(sb + dst, gsrc + (size_t)c * 8192 + (size_t)split * 4096
                                          + (size_t)seg * 16);
            }
            CP_COMMIT();
        }

        const uint32_t bbuf = B_BASE + (uint32_t)(g & 1) * B_BUF_B;

        #pragma unroll
        for (int c = 0; c < GROUP; c++) {
            const int jj = g * GROUP + c;
            const uint32_t astage = (uint32_t)(jj & 1) * A_STAGE_B;
            const uint32_t bchunk = bbuf + (uint32_t)c * B_CHUNK_B;

            if (jj + 1 < NITER) {
                #pragma unroll
                for (int i = 0; i < 4; i++)
                    xr[i] = *(const float4*)(xbase + (size_t)i * 4 * IN_DIM
                                                   + (size_t)(jj + 1) * BK);
            }

            uint32_t w1f[4][4], w2f[4][4], aH[2][4], aG[2][4];
            #pragma unroll
            for (int gg = 0; gg < 4; gg++)
                ldsm4(w1f[gg], sb + bchunk + b_ld + (uint32_t)gg * 1280);
            ldsm4(aH[0], sb + astage + a_ld);
            ldsm4(aH[1], sb + astage + a_ld + 1280);
            #pragma unroll
            for (int gg = 0; gg < 4; gg++)
                ldsm4(w2f[gg], sb + bchunk + B_OFF_W2 + b_ld + (uint32_t)gg * 1280);
            ldsm4(aG[0], sb + astage + A_OFF_H2 + a_ld);
            ldsm4(aG[1], sb + astage + A_OFF_H2 + a_ld + 1280);

            #pragma unroll
            for (int gg = 0; gg < 4; gg++)
                #pragma unroll
                for (int m = 0; m < 2; m++) {
                    mma_f32(&accM[m][(2 * gg) * 4],     aH[m], w1f[gg][0], w1f[gg][1]);
                    mma_f32(&accM[m][(2 * gg + 1) * 4], aH[m], w1f[gg][2], w1f[gg][3]);
                }
            #pragma unroll
            for (int gg = 0; gg < 4; gg++)
                #pragma unroll
                for (int m = 0; m < 2; m++) {
                    mma_f16(&accC[m][(2 * gg) * 2],     aH[m], w2f[gg][0], w2f[gg][1]);
                    mma_f16(&accC[m][(2 * gg + 1) * 2], aH[m], w2f[gg][2], w2f[gg][3]);
                }
            #pragma unroll
            for (int gg = 0; gg < 4; gg++)
                #pragma unroll
                for (int m = 0; m < 2; m++) {
                    mma_f16(&accC[m][(2 * gg) * 2],     aG[m], w1f[gg][0], w1f[gg][1]);
                    mma_f16(&accC[m][(2 * gg + 1) * 2], aG[m], w1f[gg][2], w1f[gg][3]);
                }

            if (jj + 1 < NITER) {
                char* Ab = smch + (size_t)((jj + 1) & 1) * A_STAGE_B;
                #pragma unroll
                for (int i = 0; i < 4; i++)
                    cvt_store(Ab, st_base + (uint32_t)i * 320, xr[i]);
            }
            BAR_PAIR(wm + 1);
        }

        CP_WAIT0();
        __syncthreads();
    }

    // ================= combine k-halves =================
    float* ex = (float*)smch;
    if (wk == 1) {
        const int base = wm * 3072;
        #pragma unroll
        for (int m = 0; m < 2; m++) {
            #pragma unroll
            for (int i = 0; i < 32; i++)
                ex[base + (m * 48 + i) * 32 + lane] = accM[m][i];
            #pragma unroll
            for (int i = 0; i < 16; i++)
                ((uint32_t*)ex)[base + (m * 48 + 32 + i) * 32 + lane] = accC[m][i];
        }
    }
    __syncthreads();
    if (wk == 1) return;

    uint32_t ptC[2][16];
    {
        const int base = wm * 3072;
        #pragma unroll
        for (int m = 0; m < 2; m++) {
            #pragma unroll
            for (int i = 0; i < 32; i++)
                accM[m][i] += ex[base + (m * 48 + i) * 32 + lane];
            #pragma unroll
            for (int i = 0; i < 16; i++)
                ptC[m][i] = ((uint32_t*)ex)[base + (m * 48 + 32 + i) * 32 + lane];
        }
    }

    // ================= epilogue (warps 0-7) =================
    const int q  = lane >> 2;
    const int qc = lane & 3;
    float* outIdx = out;
    float* outW   = out + 2 * (size_t)N_TOKENS;
    float* probs  = out + 4 * (size_t)N_TOKENS;

    #pragma unroll
    for (int m = 0; m < 2; m++) {
        #pragma unroll
        for (int r = 0; r < 2; r++) {
            float v[16];
            #pragma unroll
            for (int f = 0; f < 8; f++) {
                uint32_t c0 = accC[m][f * 2 + r];
                uint32_t c1 = ptC[m][f * 2 + r];
                float2 cf = __half22float2(*(__half2*)&c0);
                float2 cg = __half22float2(*(__half2*)&c1);
                v[2 * f]     = fmaf(cf.x + cg.x, INV_SCALE, accM[m][f * 4 + 2 * r]);
                v[2 * f + 1] = fmaf(cf.y + cg.y, INV_SCALE, accM[m][f * 4 + 2 * r + 1]);
            }
            float mx = v[0];
            #pragma unroll
            for (int i = 1; i < 16; i++) mx = fmaxf(mx, v[i]);
            mx = fmaxf(mx, __shfl_xor_sync(0xffffffffu, mx, 1));
            mx = fmaxf(mx, __shfl_xor_sync(0xffffffffu, mx, 2));

            float v1 = -3.4e38f, v2 = -3.4e38f;
            int   i1 = 0, i2 = 0;
            #pragma unroll
            for (int f = 0; f < 8; f++) {
                #pragma unroll
                for (int cch = 0; cch < 2; cch++) {
                    float val = v[2 * f + cch];
                    int   e   = f * 8 + qc * 2 + cch;
                    if (val > v1)      { v2 = v1; i2 = i1; v1 = val; i1 = e; }
                    else if (val > v2) { v2 = val; i2 = e; }
                }
            }
            #pragma unroll
            for (int d = 1; d <= 2; d <<= 1) {
                float ov1 = __shfl_xor_sync(0xffffffffu, v1, d);
                int   oi1 = __shfl_xor_sync(0xffffffffu, i1, d);
                float ov2 = __shfl_xor_sync(0xffffffffu, v2, d);
                int   oi2 = __shfl_xor_sync(0xffffffffu, i2, d);
                bool bet1 = (ov1 > v1) || (ov1 == v1 && oi1 < i1);
                if (bet1) {
                    bool keepOld = (v1 > ov2) || (v1 == ov2 && i1 < oi2);
                    if (keepOld) { v2 = v1; i2 = i1; } else { v2 = ov2; i2 = oi2; }
                    v1 = ov1; i1 = oi1;
                } else {
                    bool bet2 = (ov1 > v2) || (ov1 == v2 && oi1 < i2);
                    if (bet2) { v2 = ov1; i2 = oi1; }
                }
            }

            float ssum = 0.0f;
            #pragma unroll
            for (int i = 0; i < 16; i++) { v[i] = __expf(v[i] - mx); ssum += v[i]; }
            ssum += __shfl_xor_sync(0xffffffffu, ssum, 1);
            ssum += __shfl_xor_sync(0xffffffffu, ssum, 2);
            float rinv = 1.0f / ssum;

            const int row = tokenBase + wm * 32 + m * 16 + q + r * 8;
            float* pr = probs + (size_t)row * N_EXPERTS + qc * 2;
            #pragma unroll
            for (int f = 0; f < 8; f++) {
                float2 pv = make_float2(v[2 * f] * rinv, v[2 * f + 1] * rinv);
                *(float2*)(pr + f * 8) = pv;
            }
            if (qc == 0) {
                float p1 = __expf(v1 - mx), p2 = __expf(v2 - mx);
                outIdx[(size_t)row * 2 + 0] = (float)i1;
                outIdx[(size_t)row * 2 + 1] = (float)i2;
                float tw = 1.0f / (p1 + p2);
                outW[(size_t)row * 2 + 0] = p1 * tw;
                outW[(size_t)row * 2 + 1] = p2 * tw;
            }
        }
    }
}

// ---------------------------------------------------------------- launcher
extern "C" void kernel_launch(void* const* d_in, const int* in_sizes, int n_in,
                              void* d_out, int out_size) {
    const float* x = (const float*)d_in[0];
    const float* W = (const float*)d_in[1];
    float* out = (float*)d_out;

    static int configured = 0;
    if (!configured) {
        cudaFuncSetAttribute(router_mma_kernel,
                             cudaFuncAttributeMaxDynamicSharedMemorySize, SMEM_BYTES);
        configured = 1;
    }

    wsplit_kernel<<<(N_EXPERTS * IN_DIM) / 256, 256>>>(W);
    router_mma_kernel<<<GRID_CTAS, NTHREADS, SMEM_BYTES>>>(x, out);
}

// round 11
// speedup vs baseline: 1.8634x; 1.8634x over previous
#include <cuda_runtime.h>
#include <cuda_fp16.h>
#include <cstdint>

// ---------------------------------------------------------------- constants
#define N_TOKENS  65536
#define IN_DIM    2048
#define N_EXPERTS 64
#define TILE_M    256
#define BK        32
#define NITER     (IN_DIM / BK)       // 64
#define GROUP     4
#define NGROUPS   (NITER / GROUP)     // 16
#define NTHREADS  512                 // 16 warps: wm = w&7 (32-row block), wn = w>>3 (expert half)
#define GRID_CTAS (N_TOKENS / TILE_M) // 256

// ---------------- smem map (bytes) ----------------
// A staging: 2 stages x (h1 256x80 | h2 256x80)
#define A_OFF_H2   20480
#define A_STAGE_B  40960
#define B_BASE     81920
#define B_CHUNK_B  10240
#define B_OFF_W2   5120
#define B_BUF_B    (GROUP * B_CHUNK_B)          // 40960
#define SMEM_BYTES (B_BASE + 2 * B_BUF_B)       // 163840 -> 1 CTA/SM

#define SPLIT_SCALE 2048.0f
#define INV_SCALE   (1.0f / 2048.0f)

// W pack: [chunk j][split 0..1][n=0..63][k=0..31] fp16 (512 KB)
__device__ __align__(16) __half Wpack_g[NITER * 2 * N_EXPERTS * BK];

// ---------------------------------------------------------------- helpers
__device__ __forceinline__ uint32_t smem_u32(const void* p) {
    uint32_t a;
    asm("{ .reg .u64 t; cvta.to.shared.u64 t, %1; cvt.u32.u64 %0, t; }" : "=r"(a) : "l"(p));
    return a;
}

__device__ __forceinline__ void ldsm4(uint32_t* r, uint32_t addr) {
    asm volatile("ldmatrix.sync.aligned.m8n8.x4.shared.b16 {%0,%1,%2,%3}, [%4];"
                 : "=r"(r[0]), "=r"(r[1]), "=r"(r[2]), "=r"(r[3]) : "r"(addr));
}

__device__ __forceinline__ void mma_f32(float* c, const uint32_t* a,
                                        uint32_t b0, uint32_t b1) {
    asm volatile(
        "mma.sync.aligned.m16n8k16.row.col.f32.f16.f16.f32 "
        "{%0,%1,%2,%3}, {%4,%5,%6,%7}, {%8,%9}, {%0,%1,%2,%3};"
        : "+f"(c[0]), "+f"(c[1]), "+f"(c[2]), "+f"(c[3])
        : "r"(a[0]), "r"(a[1]), "r"(a[2]), "r"(a[3]), "r"(b0), "r"(b1));
}

__device__ __forceinline__ void mma_f16(uint32_t* c, const uint32_t* a,
                                        uint32_t b0, uint32_t b1) {
    asm volatile(
        "mma.sync.aligned.m16n8k16.row.col.f16.f16.f16.f16 "
        "{%0,%1}, {%2,%3,%4,%5}, {%6,%7}, {%0,%1};"
        : "+r"(c[0]), "+r"(c[1])
        : "r"(a[0]), "r"(a[1]), "r"(a[2]), "r"(a[3]), "r"(b0), "r"(b1));
}

__device__ __forceinline__ void cp_async16(uint32_t dst, const void* src) {
    asm volatile("cp.async.ca.shared.global [%0], [%1], 16;" :: "r"(dst), "l"(src));
}
#define CP_COMMIT() asm volatile("cp.async.commit_group;" ::: "memory")
#define CP_WAIT0()  asm volatile("cp.async.wait_group 0;" ::: "memory")
// pair barrier: warps wm and wm+8 (ids 1..8; id 0 reserved for __syncthreads)
#define BAR_PAIR(id) asm volatile("bar.sync %0, 64;" :: "r"(id) : "memory")

// ---------------------------------------------------------------- W split pre-kernel
__global__ void wsplit_kernel(const float* __restrict__ W) {
    int idx = blockIdx.x * 256 + threadIdx.x;
    int e = idx >> 11;
    int k = idx & 2047;
    float w = W[idx];
    __half h1 = __float2half_rn(w);
    float  r  = (w - __half2float(h1)) * SPLIT_SCALE;
    __half h2 = __float2half_rn(r);
    int j = k >> 5, kk = k & 31;
    Wpack_g[(size_t)j * 4096 + 0 * 2048 + e * 32 + kk] = h1;
    Wpack_g[(size_t)j * 4096 + 1 * 2048 + e * 32 + kk] = h2;
}

// ---------------------------------------------------------------- x conversion
__device__ __forceinline__ void cvt_store(char* Ab, uint32_t off, float4 v) {
    __half2 h1a = __floats2half2_rn(v.x, v.y);
    __half2 h1b = __floats2half2_rn(v.z, v.w);
    float2 fa = __half22float2(h1a);
    float2 fb = __half22float2(h1b);
    __half2 ra = __floats2half2_rn((v.x - fa.x) * SPLIT_SCALE, (v.y - fa.y) * SPLIT_SCALE);
    __half2 rb = __floats2half2_rn((v.z - fb.x) * SPLIT_SCALE, (v.w - fb.y) * SPLIT_SCALE);
    uint2 hh, rr;
    hh.x = *(uint32_t*)&h1a; hh.y = *(uint32_t*)&h1b;
    rr.x = *(uint32_t*)&ra;  rr.y = *(uint32_t*)&rb;
    *(uint2*)(Ab + off)            = hh;
    *(uint2*)(Ab + A_OFF_H2 + off) = rr;
}

// ---------------------------------------------------------------- main kernel
extern __shared__ __align__(16) char smch[];

__global__ void __launch_bounds__(NTHREADS, 1)
router_mma_kernel(const float* __restrict__ x, float* __restrict__ out) {
    const int tid  = threadIdx.x;
    const int w    = tid >> 5;
    const int lane = tid & 31;
    const int wm   = w & 7;      // token block: rows [wm*32, wm*32+32)
    const int wn   = w >> 3;     // expert half: experts [wn*32, wn*32+32)
    const int tokenBase = blockIdx.x * TILE_M;
    const uint32_t sb = smem_u32(smch);

    // ---- x staging: warp stages 16 rows (wm*32 + wn*16 + ...)
    const float* xbase = x + (size_t)(tokenBase + wm * 32 + wn * 16 + (lane >> 3)) * IN_DIM
                           + (lane & 7) * 4;
    const uint32_t st_base = (uint32_t)((wm * 32 + wn * 16 + (lane >> 3)) * 80
                                        + (lane & 7) * 8);

    // ---- ldmatrix offsets
    const uint32_t a_ld = (uint32_t)((wm * 32 + (lane & 15)) * 80
                                     + ((lane >> 4) & 1) * 16);
    const uint32_t b_ld = (uint32_t)((wn * 32 + (lane & 7) + ((lane >> 4) & 1) * 8) * 80
                                     + ((lane >> 3) & 1) * 16);

    float    accM[2][16];   // fp32 main: 2 m-tiles x n32 (4 n8 x 4 regs)
    uint32_t accC[2][8];    // fp16 cross (x2048 units)
    #pragma unroll
    for (int m = 0; m < 2; m++) {
        #pragma unroll
        for (int i = 0; i < 16; i++) accM[m][i] = 0.0f;
        #pragma unroll
        for (int i = 0; i < 8; i++)  accC[m][i] = 0u;
    }

    float4 xr[4];

    // ================= prologue =================
    {
        #pragma unroll
        for (int i = 0; i < 4; i++) {
            int gs    = tid + 512 * i;
            int c     = gs >> 9;
            int ws    = gs & 511;
            int split = ws >> 8;
            int seg   = ws & 255;
            uint32_t dst = B_BASE + (uint32_t)c * B_CHUNK_B + (uint32_t)split * B_OFF_W2
                         + (uint32_t)(seg >> 2) * 80 + (uint32_t)(seg & 3) * 16;
            const char* src = (const char*)Wpack_g + (size_t)c * 8192
                            + (size_t)split * 4096 + (size_t)seg * 16;
            cp_async16(sb + dst, src);
        }
        CP_COMMIT();
        #pragma unroll
        for (int i = 0; i < 4; i++)
            xr[i] = *(const float4*)(xbase + (size_t)i * 4 * IN_DIM);
        #pragma unroll
        for (int i = 0; i < 4; i++)
            cvt_store(smch, st_base + (uint32_t)i * 320, xr[i]);
        CP_WAIT0();
        __syncthreads();
    }

    // ================= main loop: 16 groups x 4 chunks =================
    for (int g = 0; g < NGROUPS; g++) {
        if (g + 1 < NGROUPS) {
            const uint32_t nbuf = B_BASE + (uint32_t)((g + 1) & 1) * B_BUF_B;
            const char* gsrc = (const char*)Wpack_g + (size_t)(g + 1) * GROUP * 8192;
            #pragma unroll
            for (int i = 0; i < 4; i++) {
                int gs    = tid + 512 * i;
                int c     = gs >> 9;
                int ws    = gs & 511;
                int split = ws >> 8;
                int seg   = ws & 255;
                uint32_t dst = nbuf + (uint32_t)c * B_CHUNK_B + (uint32_t)split * B_OFF_W2
                             + (uint32_t)(seg >> 2) * 80 + (uint32_t)(seg & 3) * 16;
                cp_async16(sb + dst, gsrc + (size_t)c * 8192 + (size_t)split * 4096
                                          + (size_t)seg * 16);
            }
            CP_COMMIT();
        }

        const uint32_t bbuf = B_BASE + (uint32_t)(g & 1) * B_BUF_B;

        #pragma unroll
        for (int c = 0; c < GROUP; c++) {
            const int jj = g * GROUP + c;
            const uint32_t astage = (uint32_t)(jj & 1) * A_STAGE_B;
            const uint32_t bchunk = bbuf + (uint32_t)c * B_CHUNK_B;

            if (jj + 1 < NITER) {
                #pragma unroll
                for (int i = 0; i < 4; i++)
                    xr[i] = *(const float4*)(xbase + (size_t)i * 4 * IN_DIM
                                                   + (size_t)(jj + 1) * BK);
            }

            // ---- compute chunk jj: 2 k16 steps, warp's n32 only ----
            #pragma unroll
            for (int kk = 0; kk < 2; kk++) {
                const uint32_t ko = (uint32_t)kk * 32;
                uint32_t w1f[2][4], w2f[2][4], aH[2][4], aG[2][4];
                #pragma unroll
                for (int gg = 0; gg < 2; gg++)
                    ldsm4(w1f[gg], sb + bchunk + b_ld + (uint32_t)gg * 1280 + ko);
                ldsm4(aH[0], sb + astage + a_ld + ko);
                ldsm4(aH[1], sb + astage + a_ld + 1280 + ko);
                #pragma unroll
                for (int gg = 0; gg < 2; gg++)
                    ldsm4(w2f[gg], sb + bchunk + B_OFF_W2 + b_ld + (uint32_t)gg * 1280 + ko);
                ldsm4(aG[0], sb + astage + A_OFF_H2 + a_ld + ko);
                ldsm4(aG[1], sb + astage + A_OFF_H2 + a_ld + 1280 + ko);

                #pragma unroll
                for (int gg = 0; gg < 2; gg++)
                    #pragma unroll
                    for (int m = 0; m < 2; m++) {
                        mma_f32(&accM[m][(2 * gg) * 4],     aH[m], w1f[gg][0], w1f[gg][1]);
                        mma_f32(&accM[m][(2 * gg + 1) * 4], aH[m], w1f[gg][2], w1f[gg][3]);
                    }
                #pragma unroll
                for (int gg = 0; gg < 2; gg++)
                    #pragma unroll
                    for (int m = 0; m < 2; m++) {
                        mma_f16(&accC[m][(2 * gg) * 2],     aH[m], w2f[gg][0], w2f[gg][1]);
                        mma_f16(&accC[m][(2 * gg + 1) * 2], aH[m], w2f[gg][2], w2f[gg][3]);
                    }
                #pragma unroll
                for (int gg = 0; gg < 2; gg++)
                    #pragma unroll
                    for (int m = 0; m < 2; m++) {
                        mma_f16(&accC[m][(2 * gg) * 2],     aG[m], w1f[gg][0], w1f[gg][1]);
                        mma_f16(&accC[m][(2 * gg + 1) * 2], aG[m], w1f[gg][2], w1f[gg][3]);
                    }
            }

            // stage next A chunk (pair-private), then pair-sync
            if (jj + 1 < NITER) {
                char* Ab = smch + (size_t)((jj + 1) & 1) * A_STAGE_B;
                #pragma unroll
                for (int i = 0; i < 4; i++)
                    cvt_store(Ab, st_base + (uint32_t)i * 320, xr[i]);
            }
            BAR_PAIR(wm + 1);
        }

        CP_WAIT0();
        __syncthreads();
    }

    // ================= epilogue =================
    // Each warp computes final logits for its n32. wn=1 publishes to smem
    // (stride 33 floats: conflict-light), wn=0 concatenates + full epilogue.
    const int q  = lane >> 2;
    const int qc = lane & 3;
    float* ex = (float*)smch;   // [256 rows][33] floats = 33.8 KB (A region reuse)

    if (wn == 1) {
        #pragma unroll
        for (int m = 0; m < 2; m++)
            #pragma unroll
            for (int r = 0; r < 2; r++) {
                const int row = wm * 32 + m * 16 + q + r * 8;
                #pragma unroll
                for (int f = 0; f < 4; f++) {
                    uint32_t cr = accC[m][f * 2 + r];
                    float2 cf = __half22float2(*(__half2*)&cr);
                    ex[row * 33 + f * 8 + qc * 2 + 0] =
                        fmaf(cf.x, INV_SCALE, accM[m][f * 4 + 2 * r]);
                    ex[row * 33 + f * 8 + qc * 2 + 1] =
                        fmaf(cf.y, INV_SCALE, accM[m][f * 4 + 2 * r + 1]);
                }
            }
    }
    __syncthreads();
    if (wn == 1) return;

    float* outIdx = out;
    float* outW   = out + 2 * (size_t)N_TOKENS;
    float* probs  = out + 4 * (size_t)N_TOKENS;

    #pragma unroll
    for (int m = 0; m < 2; m++) {
        #pragma unroll
        for (int r = 0; r < 2; r++) {
            const int rowl = wm * 32 + m * 16 + q + r * 8;
            float v[16];
            #pragma unroll
            for (int f = 0; f < 4; f++) {           // own experts 0-31
                uint32_t cr = accC[m][f * 2 + r];
                float2 cf = __half22float2(*(__half2*)&cr);
                v[2 * f]     = fmaf(cf.x, INV_SCALE, accM[m][f * 4 + 2 * r]);
                v[2 * f + 1] = fmaf(cf.y, INV_SCALE, accM[m][f * 4 + 2 * r + 1]);
            }
            #pragma unroll
            for (int f = 4; f < 8; f++) {           // partner experts 32-63
                v[2 * f]     = ex[rowl * 33 + (f - 4) * 8 + qc * 2 + 0];
                v[2 * f + 1] = ex[rowl * 33 + (f - 4) * 8 + qc * 2 + 1];
            }
            float mx = v[0];
            #pragma unroll
            for (int i = 1; i < 16; i++) mx = fmaxf(mx, v[i]);
            mx = fmaxf(mx, __shfl_xor_sync(0xffffffffu, mx, 1));
            mx = fmaxf(mx, __shfl_xor_sync(0xffffffffu, mx, 2));

            float v1 = -3.4e38f, v2 = -3.4e38f;
            int   i1 = 0, i2 = 0;
            #pragma unroll
            for (int f = 0; f < 8; f++) {
                #pragma unroll
                for (int cch = 0; cch < 2; cch++) {
                    float val = v[2 * f + cch];
                    int   e   = f * 8 + qc * 2 + cch;
                    if (val > v1)      { v2 = v1; i2 = i1; v1 = val; i1 = e; }
                    else if (val > v2) { v2 = val; i2 = e; }
                }
            }
            #pragma unroll
            for (int d = 1; d <= 2; d <<= 1) {
                float ov1 = __shfl_xor_sync(0xffffffffu, v1, d);
                int   oi1 = __shfl_xor_sync(0xffffffffu, i1, d);
                float ov2 = __shfl_xor_sync(0xffffffffu, v2, d);
                int   oi2 = __shfl_xor_sync(0xffffffffu, i2, d);
                bool bet1 = (ov1 > v1) || (ov1 == v1 && oi1 < i1);
                if (bet1) {
                    bool keepOld = (v1 > ov2) || (v1 == ov2 && i1 < oi2);
                    if (keepOld) { v2 = v1; i2 = i1; } else { v2 = ov2; i2 = oi2; }
                    v1 = ov1; i1 = oi1;
                } else {
                    bool bet2 = (ov1 > v2) || (ov1 == v2 && oi1 < i2);
                    if (bet2) { v2 = ov1; i2 = oi1; }
                }
            }

            float ssum = 0.0f;
            #pragma unroll
            for (int i = 0; i < 16; i++) { v[i] = __expf(v[i] - mx); ssum += v[i]; }
            ssum += __shfl_xor_sync(0xffffffffu, ssum, 1);
            ssum += __shfl_xor_sync(0xffffffffu, ssum, 2);
            float rinv = 1.0f / ssum;

            const int row = tokenBase + rowl;
            float* pr = probs + (size_t)row * N_EXPERTS + qc * 2;
            #pragma unroll
            for (int f = 0; f < 8; f++) {
                float2 pv = make_float2(v[2 * f] * rinv, v[2 * f + 1] * rinv);
                *(float2*)(pr + f * 8) = pv;
            }
            if (qc == 0) {
                float p1 = __expf(v1 - mx), p2 = __expf(v2 - mx);
                outIdx[(size_t)row * 2 + 0] = (float)i1;
                outIdx[(size_t)row * 2 + 1] = (float)i2;
                float tw = 1.0f / (p1 + p2);
                outW[(size_t)row * 2 + 0] = p1 * tw;
                outW[(size_t)row * 2 + 1] = p2 * tw;
            }
        }
    }
}

// ---------------------------------------------------------------- launcher
extern "C" void kernel_launch(void* const* d_in, const int* in_sizes, int n_in,
                              void* d_out, int out_size) {
    const float* x = (const float*)d_in[0];
    const float* W = (const float*)d_in[1];
    float* out = (float*)d_out;

    static int configured = 0;
    if (!configured) {
        cudaFuncSetAttribute(router_mma_kernel,
                             cudaFuncAttributeMaxDynamicSharedMemorySize, SMEM_BYTES);
        configured = 1;
    }

    wsplit_kernel<<<(N_EXPERTS * IN_DIM) / 256, 256>>>(W);
    router_mma_kernel<<<GRID_CTAS, NTHREADS, SMEM_BYTES>>>(x, out);
}